// round 1
// baseline (speedup 1.0000x reference)
#include <cuda_runtime.h>
#include <math.h>

// Problem: B=4096, N=16384, fp32.
//   x        = nan_checker(output)            [B,N]  (NaN/Inf -> 0)
//   g[i]     = x[i] - x[(i-1) mod N]          (per row, circular)
//   std      = sqrt(var_grad)                 [N]
//   mask     = g < mean-4*std || g > mean+4*std
//   out      = mask ? 0 : x
//
// HBM-bound: 256MB in + 256MB out. Strategy: float4 vectors, warp shuffle
// for the left neighbor (lane0 does one extra scalar load, L1/L2-hit),
// column stats (128KB) stay L2-resident across all 4096 rows.

#define K_SIGMA 4.0f

__device__ __forceinline__ float sanitize(float v) {
    // NaN or Inf -> 0
    return isfinite(v) ? v : 0.0f;
}

__global__ __launch_bounds__(256)
void correction_kernel(const float* __restrict__ x,
                       const float* __restrict__ mean_grad,
                       const float* __restrict__ var_grad,
                       float* __restrict__ out,
                       int n_vec_per_row,   // N/4
                       int N)
{
    // One thread = one float4. Warps are contiguous within a row
    // (n_vec_per_row = 4096 is a multiple of 32, so no warp straddles rows).
    long long v = (long long)blockIdx.x * blockDim.x + threadIdx.x;
    int row  = (int)(v / n_vec_per_row);
    int colv = (int)(v % n_vec_per_row);

    const float4* xrow4 = reinterpret_cast<const float4*>(x + (long long)row * N);
    float4 xv = xrow4[colv];
    xv.x = sanitize(xv.x);
    xv.y = sanitize(xv.y);
    xv.z = sanitize(xv.z);
    xv.w = sanitize(xv.w);

    // Left neighbor of element 0 of this vector:
    //  - lanes 1..31: previous lane's .w via shuffle (already sanitized)
    //  - lane 0: scalar load of x[row, colv*4 - 1]  (or x[row, N-1] if colv==0)
    unsigned lane = threadIdx.x & 31u;
    float prev = __shfl_up_sync(0xFFFFFFFFu, xv.w, 1);
    if (lane == 0) {
        int pc = (colv == 0) ? (N - 1) : (colv * 4 - 1);
        prev = sanitize(x[(long long)row * N + pc]);
    }

    // Column stats (L2-resident, reused by every row)
    float4 mg = reinterpret_cast<const float4*>(mean_grad)[colv];
    float4 vg = reinterpret_cast<const float4*>(var_grad)[colv];

    float4 o;
    {
        float g = xv.x - prev;
        float s = K_SIGMA * sqrtf(vg.x);
        o.x = (g < mg.x - s || g > mg.x + s) ? 0.0f : xv.x;
    }
    {
        float g = xv.y - xv.x;
        float s = K_SIGMA * sqrtf(vg.y);
        o.y = (g < mg.y - s || g > mg.y + s) ? 0.0f : xv.y;
    }
    {
        float g = xv.z - xv.y;
        float s = K_SIGMA * sqrtf(vg.z);
        o.z = (g < mg.z - s || g > mg.z + s) ? 0.0f : xv.z;
    }
    {
        float g = xv.w - xv.z;
        float s = K_SIGMA * sqrtf(vg.w);
        o.w = (g < mg.w - s || g > mg.w + s) ? 0.0f : xv.w;
    }

    reinterpret_cast<float4*>(out + (long long)row * N)[colv] = o;
}

extern "C" void kernel_launch(void* const* d_in, const int* in_sizes, int n_in,
                              void* d_out, int out_size) {
    const float* x         = (const float*)d_in[0];  // output [B,N]
    const float* mean_grad = (const float*)d_in[1];  // [N]
    const float* var_grad  = (const float*)d_in[2];  // [N]
    float* out             = (float*)d_out;

    int N = in_sizes[1];                 // 16384
    long long total = (long long)in_sizes[0];  // B*N
    int B = (int)(total / N);

    int n_vec_per_row = N / 4;
    long long n_vec = (long long)B * n_vec_per_row;
    int threads = 256;
    int blocks = (int)((n_vec + threads - 1) / threads);

    correction_kernel<<<blocks, threads>>>(x, mean_grad, var_grad, out,
                                           n_vec_per_row, N);
}

// round 2
// speedup vs baseline: 1.1155x; 1.1155x over previous
#include <cuda_runtime.h>
#include <math.h>

// B=4096, N=16384, fp32. HBM-bound elementwise stencil:
//   x = nan_checker(output); g[i] = x[i]-x[(i-1)%N];
//   out = (g outside mean±4*sqrt(var)) ? 0 : x
//
// R2: 2D grid (no div/mod), 2 float4/thread (block-strided, coalesced),
// streaming loads/stores, shuffle for left neighbor.

#define K_SIGMA 4.0f
#define VPT 2          // float4 vectors per thread
#define TPB 256        // threads per block

__device__ __forceinline__ float sanitize(float v) {
    return isfinite(v) ? v : 0.0f;
}

__device__ __forceinline__ float4 sanitize4(float4 v) {
    v.x = sanitize(v.x); v.y = sanitize(v.y);
    v.z = sanitize(v.z); v.w = sanitize(v.w);
    return v;
}

__device__ __forceinline__ float4 apply4(float4 xv, float prev,
                                         float4 mg, float4 vg) {
    float4 o;
    float s, g;
    g = xv.x - prev;  s = K_SIGMA * sqrtf(vg.x);
    o.x = (g < mg.x - s || g > mg.x + s) ? 0.0f : xv.x;
    g = xv.y - xv.x;  s = K_SIGMA * sqrtf(vg.y);
    o.y = (g < mg.y - s || g > mg.y + s) ? 0.0f : xv.y;
    g = xv.z - xv.y;  s = K_SIGMA * sqrtf(vg.z);
    o.z = (g < mg.z - s || g > mg.z + s) ? 0.0f : xv.z;
    g = xv.w - xv.z;  s = K_SIGMA * sqrtf(vg.w);
    o.w = (g < mg.w - s || g > mg.w + s) ? 0.0f : xv.w;
    return o;
}

__global__ __launch_bounds__(TPB)
void correction_kernel(const float* __restrict__ x,
                       const float* __restrict__ mean_grad,
                       const float* __restrict__ var_grad,
                       float* __restrict__ out,
                       int N)
{
    const int row = blockIdx.y;
    const long long rowOff = (long long)row * N;
    const float4* xr  = reinterpret_cast<const float4*>(x + rowOff);
    float4*       or4 = reinterpret_cast<float4*>(out + rowOff);
    const float4* mg4 = reinterpret_cast<const float4*>(mean_grad);
    const float4* vg4 = reinterpret_cast<const float4*>(var_grad);

    const int baseVec = blockIdx.x * (TPB * VPT);
    const unsigned lane = threadIdx.x & 31u;

    // Front-batched loads: both slots issued before any compute (MLP).
    int   cv[VPT];
    float4 xv[VPT];
    #pragma unroll
    for (int i = 0; i < VPT; i++) {
        cv[i] = baseVec + i * TPB + threadIdx.x;
        xv[i] = sanitize4(__ldcs(&xr[cv[i]]));
    }

    #pragma unroll
    for (int i = 0; i < VPT; i++) {
        // Left neighbor of first element: prior lane's .w, lane0 loads scalar.
        float prev = __shfl_up_sync(0xFFFFFFFFu, xv[i].w, 1);
        if (lane == 0) {
            int pc = (cv[i] == 0) ? (N - 1) : (cv[i] * 4 - 1);
            prev = sanitize(__ldg(&x[rowOff + pc]));
        }
        float4 mg = __ldg(&mg4[cv[i]]);
        float4 vg = __ldg(&vg4[cv[i]]);
        __stcs(&or4[cv[i]], apply4(xv[i], prev, mg, vg));
    }
}

extern "C" void kernel_launch(void* const* d_in, const int* in_sizes, int n_in,
                              void* d_out, int out_size) {
    const float* x         = (const float*)d_in[0];
    const float* mean_grad = (const float*)d_in[1];
    const float* var_grad  = (const float*)d_in[2];
    float* out             = (float*)d_out;

    int N = in_sizes[1];                       // 16384
    long long total = (long long)in_sizes[0];  // B*N
    int B = (int)(total / N);

    int n_vec_per_row = N / 4;                 // 4096
    dim3 grid(n_vec_per_row / (TPB * VPT), B); // (8, 4096)
    correction_kernel<<<grid, TPB>>>(x, mean_grad, var_grad, out, N);
}